// round 1
// baseline (speedup 1.0000x reference)
#include <cuda_runtime.h>

#define VOCAB 100000
#define DIM   300
#define BATCH 65536
#define KNEG  10
#define NF4   75           // DIM/4 float4 per row (1200B rows, 16B aligned)
#define WARPS_PER_BLOCK 8
#define NBLOCKS (BATCH / WARPS_PER_BLOCK)   // 8192

__device__ float g_partials[NBLOCKS];

__device__ __forceinline__ float softplus_f(float x) {
    // log(1 + exp(x)), numerically stable
    return (x > 0.f) ? x + log1pf(__expf(-x)) : log1pf(__expf(x));
}

__device__ __forceinline__ float dot12(const float4& a0, const float4& a1, const float4& a2,
                                       const float4& b0, const float4& b1, const float4& b2) {
    float p;
    p  = a0.x * b0.x; p = fmaf(a0.y, b0.y, p); p = fmaf(a0.z, b0.z, p); p = fmaf(a0.w, b0.w, p);
    p  = fmaf(a1.x, b1.x, p); p = fmaf(a1.y, b1.y, p); p = fmaf(a1.z, b1.z, p); p = fmaf(a1.w, b1.w, p);
    p  = fmaf(a2.x, b2.x, p); p = fmaf(a2.y, b2.y, p); p = fmaf(a2.z, b2.z, p); p = fmaf(a2.w, b2.w, p);
    return p;
}

__global__ __launch_bounds__(WARPS_PER_BLOCK * 32)
void sg_loss_kernel(const float* __restrict__ u_w,
                    const float* __restrict__ v_w,
                    const int*   __restrict__ pos_u,
                    const int*   __restrict__ pos_v,
                    const int*   __restrict__ neg_v) {
    const int warp = threadIdx.x >> 5;
    const int lane = threadIdx.x & 31;
    const int b = blockIdx.x * WARPS_PER_BLOCK + warp;   // grid sized exactly to BATCH

    const float4 zero4 = make_float4(0.f, 0.f, 0.f, 0.f);
    const bool has1 = (lane + 32) < NF4;   // lanes 0..42
    const bool has2 = (lane + 64) < NF4;   // lanes 0..10

    // ---- gather emb_u into registers ----
    const float4* u_row = reinterpret_cast<const float4*>(u_w + (long long)pos_u[b] * DIM);
    float4 u0 = u_row[lane];
    float4 u1 = has1 ? u_row[lane + 32] : zero4;
    float4 u2 = has2 ? u_row[lane + 64] : zero4;

    // ---- 11 v-row indices: [0]=pos_v, [1..10]=neg_v ----
    int vidx[KNEG + 1];
    vidx[0] = pos_v[b];
#pragma unroll
    for (int k = 0; k < KNEG; k++) vidx[k + 1] = neg_v[b * KNEG + k];

    float loss = 0.f;
#pragma unroll
    for (int j = 0; j < KNEG + 1; j++) {
        const float4* v_row = reinterpret_cast<const float4*>(v_w + (long long)vidx[j] * DIM);
        float4 v0 = v_row[lane];
        float4 v1 = has1 ? v_row[lane + 32] : zero4;
        float4 v2 = has2 ? v_row[lane + 64] : zero4;

        float p = dot12(u0, u1, u2, v0, v1, v2);
#pragma unroll
        for (int off = 16; off; off >>= 1)
            p += __shfl_xor_sync(0xffffffffu, p, off);

        float s = fminf(fmaxf(p, -10.f), 10.f);
        // pos: -log_sigmoid(s) = softplus(-s);  neg: -log_sigmoid(-s) = softplus(s)
        loss += (j == 0) ? softplus_f(-s) : softplus_f(s);
    }

    __shared__ float sloss[WARPS_PER_BLOCK];
    if (lane == 0) sloss[warp] = loss;
    __syncthreads();
    if (threadIdx.x == 0) {
        float t = 0.f;
#pragma unroll
        for (int i = 0; i < WARPS_PER_BLOCK; i++) t += sloss[i];
        g_partials[blockIdx.x] = t;
    }
}

__global__ void sg_reduce_kernel(float* __restrict__ out) {
    __shared__ float s[1024];
    float t = 0.f;
    for (int i = threadIdx.x; i < NBLOCKS; i += 1024) t += g_partials[i];
    s[threadIdx.x] = t;
    __syncthreads();
#pragma unroll
    for (int off = 512; off; off >>= 1) {
        if (threadIdx.x < off) s[threadIdx.x] += s[threadIdx.x + off];
        __syncthreads();
    }
    if (threadIdx.x == 0) out[0] = s[0] * (1.0f / (float)BATCH);
}

extern "C" void kernel_launch(void* const* d_in, const int* in_sizes, int n_in,
                              void* d_out, int out_size) {
    const float* u_w   = (const float*)d_in[0];   // u_weight [VOCAB, DIM]
    const float* v_w   = (const float*)d_in[1];   // v_weight [VOCAB, DIM]
    const int*   pos_u = (const int*)  d_in[2];   // [B]
    const int*   pos_v = (const int*)  d_in[3];   // [B]
    const int*   neg_v = (const int*)  d_in[4];   // [B, K]
    float* out = (float*)d_out;

    sg_loss_kernel<<<NBLOCKS, WARPS_PER_BLOCK * 32>>>(u_w, v_w, pos_u, pos_v, neg_v);
    sg_reduce_kernel<<<1, 1024>>>(out);
}